// round 6
// baseline (speedup 1.0000x reference)
#include <cuda_runtime.h>
#include <cuda_bf16.h>
#include <math.h>

// Problem constants (fixed by reference setup_inputs)
#define BB 8
#define TT 16
#define CC 64
#define NN 4096          // H*W
#define KSEL 2048        // keep_k = N*(1-0.5)

// Scratch (device globals — no allocation allowed)
__device__ float g_partial[BB * TT * NN];            // sqrt(sum_c x^2) per (b,t,n), 2 MB
__device__ unsigned g_maskbits[BB * (NN / 32)];      // 1 bit per (b,n), 4 KB

// ---------------------------------------------------------------------------
// Kernel A: copy x -> out (plain stores: dirty, L2-resident) while computing
// partial = sqrt(sum_c x^2). x reads use __ldcs (never needed again).
// Same c-ascending sum order as all prior rounds (rel_err=0 verified).
// ---------------------------------------------------------------------------
__global__ void __launch_bounds__(256) k_copy_partial(const float* __restrict__ x,
                                                      float* __restrict__ out) {
    int idx = blockIdx.x * 256 + threadIdx.x;          // [0, B*T*N)
    int n  = idx & (NN - 1);
    int bt = idx >> 12;                                // b*T + t
    const float* p = x + (size_t)bt * CC * NN + n;
    float* q = out + (size_t)bt * CC * NN + n;
    float acc = 0.0f;
#pragma unroll
    for (int c = 0; c < CC; ++c) {
        float v = __ldcs(&p[(size_t)c * NN]);
        q[(size_t)c * NN] = v;
        acc += v * v;
    }
    g_partial[idx] = sqrtf(acc);
}

// ---------------------------------------------------------------------------
// Kernel 2 (R4 form, verified): per-batch exact top-K -> mask bits.
// Atomic-free 2-bit radix select, forced-bit-pair skip, 1 barrier/iteration.
// ---------------------------------------------------------------------------
__device__ __forceinline__ unsigned long long warp_sum_u64(unsigned long long v) {
#pragma unroll
    for (int d = 16; d; d >>= 1) v += __shfl_xor_sync(0xffffffffu, v, d);
    return v;
}

__global__ void __launch_bounds__(1024, 1) k_select() {
    __shared__ unsigned long long s_red64[2][32];  // double-buffered per-warp counts
    __shared__ unsigned s_u32[66];                 // OR/AND reduction
    __shared__ unsigned s_mask[NN / 32];           // 128 words
    __shared__ int s_scan[32];
    __shared__ int s_int[1];

    const int b    = blockIdx.x;
    const int j    = threadIdx.x;              // 0..1023
    const int lane = j & 31;
    const int wid  = j >> 5;

    // --- scores: 4 per thread, sequential over t (bit-exact vs reference) ---
    const float4* part = (const float4*)g_partial;
    float s0 = 0.f, s1 = 0.f, s2 = 0.f, s3 = 0.f;
#pragma unroll
    for (int t = 0; t < TT; ++t) {
        float4 f = part[(size_t)(b * TT + t) * (NN / 4) + j];
        s0 += f.x; s1 += f.y; s2 += f.z; s3 += f.w;
    }
    const float inv = 1.0f / (float)TT;
    unsigned u0 = __float_as_uint(s0 * inv);
    unsigned u1 = __float_as_uint(s1 * inv);
    unsigned u2 = __float_as_uint(s2 * inv);
    unsigned u3 = __float_as_uint(s3 * inv);

    if (j < NN / 32) s_mask[j] = 0u;

    // --- block OR / AND of all score bits ---
    unsigned ov = u0 | u1 | u2 | u3;
    unsigned av = u0 & u1 & u2 & u3;
#pragma unroll
    for (int d = 16; d; d >>= 1) {
        ov |= __shfl_xor_sync(0xffffffffu, ov, d);
        av &= __shfl_xor_sync(0xffffffffu, av, d);
    }
    if (lane == 0) { s_u32[wid] = ov; s_u32[32 + wid] = av; }
    __syncthreads();
    {
        unsigned o2 = s_u32[lane], a2 = s_u32[32 + lane];
#pragma unroll
        for (int d = 16; d; d >>= 1) {
            o2 |= __shfl_xor_sync(0xffffffffu, o2, d);
            a2 &= __shfl_xor_sync(0xffffffffu, a2, d);
        }
        if (j == 0) { s_u32[64] = o2; s_u32[65] = a2; }
    }
    __syncthreads();
    const unsigned orv  = s_u32[64];
    const unsigned andv = s_u32[65];
    const unsigned diff = orv ^ andv;

    // --- 2-bit radix select: largest thr with count(u >= thr) >= KSEL ---
    unsigned thr = 0u;
    int par = 0;
#pragma unroll
    for (int p = 15; p >= 0; --p) {
        unsigned m2 = 3u << (2 * p);
        if ((diff & m2) == 0u) {               // both bits uniform across block
            thr |= (andv & m2);
            continue;
        }
        unsigned c1 = thr | (1u << (2 * p));
        unsigned c2 = thr | (2u << (2 * p));
        unsigned c3 = thr | (3u << (2 * p));
        int n1 = (u0 >= c1) + (u1 >= c1) + (u2 >= c1) + (u3 >= c1);
        int n2 = (u0 >= c2) + (u1 >= c2) + (u2 >= c2) + (u3 >= c2);
        int n3 = (u0 >= c3) + (u1 >= c3) + (u2 >= c3) + (u3 >= c3);
        unsigned long long pk = (unsigned long long)n1
                              | ((unsigned long long)n2 << 20)
                              | ((unsigned long long)n3 << 40);
        pk = warp_sum_u64(pk);
        if (lane == 0) s_red64[par][wid] = pk;
        __syncthreads();
        unsigned long long tot = warp_sum_u64(s_red64[par][lane]);
        int N1 = (int)(tot & 0xFFFFFull);
        int N2 = (int)((tot >> 20) & 0xFFFFFull);
        int N3 = (int)((tot >> 40) & 0xFFFFFull);
        if      (N3 >= KSEL) thr = c3;
        else if (N2 >= KSEL) thr = c2;
        else if (N1 >= KSEL) thr = c1;
        par ^= 1;
    }
    __syncthreads();   // protect s_red64 before reuse below

    // --- strictly-greater count (ties admitted by lowest index) ---
    {
        unsigned long long pk =
            (unsigned long long)((u0 > thr) + (u1 > thr) + (u2 > thr) + (u3 > thr));
        pk = warp_sum_u64(pk);
        if (lane == 0) s_red64[0][wid] = pk;
        __syncthreads();
        unsigned long long tot = warp_sum_u64(s_red64[0][lane]);
        if (j == 0) s_int[0] = (int)tot;
        __syncthreads();
    }
    int need = KSEL - s_int[0];

    // --- exclusive scan over threads of per-thread equal-count ---
    int e = (u0 == thr) + (u1 == thr) + (u2 == thr) + (u3 == thr);
    int v = e;
#pragma unroll
    for (int d = 1; d < 32; d <<= 1) {
        int t = __shfl_up_sync(0xffffffffu, v, d);
        if (lane >= d) v += t;
    }
    if (lane == 31) s_scan[wid] = v;
    __syncthreads();
    if (wid == 0) {
        int w = s_scan[lane];
#pragma unroll
        for (int d = 1; d < 32; d <<= 1) {
            int t = __shfl_up_sync(0xffffffffu, w, d);
            if (lane >= d) w += t;
        }
        s_scan[lane] = w;
    }
    __syncthreads();
    int excl = v - e + (wid ? s_scan[wid - 1] : 0);

    // --- mask nibble for n = 4j..4j+3 ---
    unsigned nib = 0;
    int r = excl;
    unsigned uu[4] = {u0, u1, u2, u3};
#pragma unroll
    for (int i = 0; i < 4; ++i) {
        if (uu[i] > thr) {
            nib |= 1u << i;
        } else if (uu[i] == thr) {
            if (r < need) nib |= 1u << i;
            ++r;
        }
    }
    atomicOr(&s_mask[j >> 3], nib << ((j & 7) * 4));
    __syncthreads();
    if (j < NN / 32) g_maskbits[b * (NN / 32) + j] = s_mask[j];
}

// ---------------------------------------------------------------------------
// Kernel B: zero dropped tokens IN-PLACE on out, reverse block order so the
// first touches hit the dirty tail Kernel A just wrote into L2.
//   nib == 0xF : fully kept  -> touch nothing (A's copy already correct)
//   nib == 0x0 : fully dropped -> write zeros, no read
//   mixed      : read-modify-write the float4
// ---------------------------------------------------------------------------
__global__ void __launch_bounds__(256) k_zero(float4* __restrict__ o4) {
    unsigned blk = gridDim.x - 1 - blockIdx.x;     // reverse traversal
    unsigned i = blk * 256 + threadIdx.x;          // [0, 8388608)
    int n4 = i & ((NN / 4) - 1);
    int b  = i >> 20;
    int n  = n4 << 2;
    unsigned bits = (g_maskbits[(b << 7) + (n >> 5)] >> (n & 31)) & 0xFu;
    if (bits == 0xFu) return;                      // already correct in out
    float4 v;
    if (bits == 0u) {
        v = make_float4(0.f, 0.f, 0.f, 0.f);       // write-only
    } else {
        v = o4[(size_t)i];
        v.x = (bits & 1u) ? v.x : 0.0f;
        v.y = (bits & 2u) ? v.y : 0.0f;
        v.z = (bits & 4u) ? v.z : 0.0f;
        v.w = (bits & 8u) ? v.w : 0.0f;
    }
    o4[(size_t)i] = v;
}

// ---------------------------------------------------------------------------
extern "C" void kernel_launch(void* const* d_in, const int* in_sizes, int n_in,
                              void* d_out, int out_size) {
    const float* x = (const float*)d_in[0];
    float* out = (float*)d_out;

    // Kernel A: B*T*N = 524288 threads (copy + partial scores)
    k_copy_partial<<<(BB * TT * NN) / 256, 256>>>(x, out);

    // Kernel 2: one 1024-thread block per batch
    k_select<<<BB, 1024>>>();

    // Kernel B: 8388608 float4 elements, 1 per thread, in-place zeroing
    k_zero<<<(BB * TT * CC * NN / 4) / 256, 256>>>((float4*)out);
}

// round 7
// speedup vs baseline: 1.5352x; 1.5352x over previous
#include <cuda_runtime.h>
#include <cuda_bf16.h>
#include <math.h>

// Problem constants (fixed by reference setup_inputs)
#define BB 8
#define TT 16
#define CC 64
#define NN 4096          // H*W
#define KSEL 2048        // keep_k = N*(1-0.5)

// Scratch (device globals — no allocation allowed)
__device__ float g_partial[BB * TT * NN];            // sqrt(sum_c x^2) per (b,t,n), 2 MB
__device__ unsigned g_maskbits[BB * (NN / 32)];      // 1 bit per (b,n), 4 KB

// ---------------------------------------------------------------------------
// Kernel 1 (R1/R5 form, 24.3us measured): partial = sqrt(sum_c x[b,t,c,n]^2)
// Plain loads: x lines populate L2 normally (the residue k_mask harvests).
// ---------------------------------------------------------------------------
__global__ void __launch_bounds__(256) k_partial(const float* __restrict__ x) {
    int idx = blockIdx.x * 256 + threadIdx.x;          // [0, B*T*N)
    int n  = idx & (NN - 1);
    int bt = idx >> 12;                                // b*T + t
    const float* p = x + (size_t)bt * CC * NN + n;
    float acc = 0.0f;
#pragma unroll
    for (int c = 0; c < CC; ++c) {
        float v = p[(size_t)c * NN];
        acc += v * v;
    }
    g_partial[idx] = sqrtf(acc);
}

// ---------------------------------------------------------------------------
// Kernel 2 (R4 form, verified): per-batch exact top-K -> mask bits.
// Atomic-free 2-bit radix select, forced-bit-pair skip, 1 barrier/iteration.
// ---------------------------------------------------------------------------
__device__ __forceinline__ unsigned long long warp_sum_u64(unsigned long long v) {
#pragma unroll
    for (int d = 16; d; d >>= 1) v += __shfl_xor_sync(0xffffffffu, v, d);
    return v;
}

__global__ void __launch_bounds__(1024, 1) k_select() {
    __shared__ unsigned long long s_red64[2][32];  // double-buffered per-warp counts
    __shared__ unsigned s_u32[66];                 // OR/AND reduction
    __shared__ unsigned s_mask[NN / 32];           // 128 words
    __shared__ int s_scan[32];
    __shared__ int s_int[1];

    const int b    = blockIdx.x;
    const int j    = threadIdx.x;              // 0..1023
    const int lane = j & 31;
    const int wid  = j >> 5;

    // --- scores: 4 per thread, sequential over t (bit-exact vs reference) ---
    const float4* part = (const float4*)g_partial;
    float s0 = 0.f, s1 = 0.f, s2 = 0.f, s3 = 0.f;
#pragma unroll
    for (int t = 0; t < TT; ++t) {
        float4 f = part[(size_t)(b * TT + t) * (NN / 4) + j];
        s0 += f.x; s1 += f.y; s2 += f.z; s3 += f.w;
    }
    const float inv = 1.0f / (float)TT;
    unsigned u0 = __float_as_uint(s0 * inv);
    unsigned u1 = __float_as_uint(s1 * inv);
    unsigned u2 = __float_as_uint(s2 * inv);
    unsigned u3 = __float_as_uint(s3 * inv);

    if (j < NN / 32) s_mask[j] = 0u;

    // --- block OR / AND of all score bits ---
    unsigned ov = u0 | u1 | u2 | u3;
    unsigned av = u0 & u1 & u2 & u3;
#pragma unroll
    for (int d = 16; d; d >>= 1) {
        ov |= __shfl_xor_sync(0xffffffffu, ov, d);
        av &= __shfl_xor_sync(0xffffffffu, av, d);
    }
    if (lane == 0) { s_u32[wid] = ov; s_u32[32 + wid] = av; }
    __syncthreads();
    {
        unsigned o2 = s_u32[lane], a2 = s_u32[32 + lane];
#pragma unroll
        for (int d = 16; d; d >>= 1) {
            o2 |= __shfl_xor_sync(0xffffffffu, o2, d);
            a2 &= __shfl_xor_sync(0xffffffffu, a2, d);
        }
        if (j == 0) { s_u32[64] = o2; s_u32[65] = a2; }
    }
    __syncthreads();
    const unsigned orv  = s_u32[64];
    const unsigned andv = s_u32[65];
    const unsigned diff = orv ^ andv;

    // --- 2-bit radix select: largest thr with count(u >= thr) >= KSEL ---
    unsigned thr = 0u;
    int par = 0;
#pragma unroll
    for (int p = 15; p >= 0; --p) {
        unsigned m2 = 3u << (2 * p);
        if ((diff & m2) == 0u) {               // both bits uniform across block
            thr |= (andv & m2);
            continue;
        }
        unsigned c1 = thr | (1u << (2 * p));
        unsigned c2 = thr | (2u << (2 * p));
        unsigned c3 = thr | (3u << (2 * p));
        int n1 = (u0 >= c1) + (u1 >= c1) + (u2 >= c1) + (u3 >= c1);
        int n2 = (u0 >= c2) + (u1 >= c2) + (u2 >= c2) + (u3 >= c2);
        int n3 = (u0 >= c3) + (u1 >= c3) + (u2 >= c3) + (u3 >= c3);
        unsigned long long pk = (unsigned long long)n1
                              | ((unsigned long long)n2 << 20)
                              | ((unsigned long long)n3 << 40);
        pk = warp_sum_u64(pk);
        if (lane == 0) s_red64[par][wid] = pk;
        __syncthreads();
        unsigned long long tot = warp_sum_u64(s_red64[par][lane]);
        int N1 = (int)(tot & 0xFFFFFull);
        int N2 = (int)((tot >> 20) & 0xFFFFFull);
        int N3 = (int)((tot >> 40) & 0xFFFFFull);
        if      (N3 >= KSEL) thr = c3;
        else if (N2 >= KSEL) thr = c2;
        else if (N1 >= KSEL) thr = c1;
        par ^= 1;
    }
    __syncthreads();   // protect s_red64 before reuse below

    // --- strictly-greater count (ties admitted by lowest index) ---
    {
        unsigned long long pk =
            (unsigned long long)((u0 > thr) + (u1 > thr) + (u2 > thr) + (u3 > thr));
        pk = warp_sum_u64(pk);
        if (lane == 0) s_red64[0][wid] = pk;
        __syncthreads();
        unsigned long long tot = warp_sum_u64(s_red64[0][lane]);
        if (j == 0) s_int[0] = (int)tot;
        __syncthreads();
    }
    int need = KSEL - s_int[0];

    // --- exclusive scan over threads of per-thread equal-count ---
    int e = (u0 == thr) + (u1 == thr) + (u2 == thr) + (u3 == thr);
    int v = e;
#pragma unroll
    for (int d = 1; d < 32; d <<= 1) {
        int t = __shfl_up_sync(0xffffffffu, v, d);
        if (lane >= d) v += t;
    }
    if (lane == 31) s_scan[wid] = v;
    __syncthreads();
    if (wid == 0) {
        int w = s_scan[lane];
#pragma unroll
        for (int d = 1; d < 32; d <<= 1) {
            int t = __shfl_up_sync(0xffffffffu, w, d);
            if (lane >= d) w += t;
        }
        s_scan[lane] = w;
    }
    __syncthreads();
    int excl = v - e + (wid ? s_scan[wid - 1] : 0);

    // --- mask nibble for n = 4j..4j+3 ---
    unsigned nib = 0;
    int r = excl;
    unsigned uu[4] = {u0, u1, u2, u3};
#pragma unroll
    for (int i = 0; i < 4; ++i) {
        if (uu[i] > thr) {
            nib |= 1u << i;
        } else if (uu[i] == thr) {
            if (r < need) nib |= 1u << i;
            ++r;
        }
    }
    atomicOr(&s_mask[j >> 3], nib << ((j & 7) * 4));
    __syncthreads();
    if (j < NN / 32) g_maskbits[b * (NN / 32) + j] = s_mask[j];
}

// ---------------------------------------------------------------------------
// Kernel 3: R5 body with ONE change — stores are __stwt (write-through, no
// L2 dirty-line allocation) so the output stream cannot evict k_partial's
// x residue. Reads stay __ldcs, block order stays reversed.
// ---------------------------------------------------------------------------
__global__ void __launch_bounds__(256) k_mask(const float4* __restrict__ x4,
                                              float4* __restrict__ o4) {
    unsigned blk = gridDim.x - 1 - blockIdx.x;     // reverse traversal
    unsigned i = blk * 256 + threadIdx.x;          // [0, 8388608)
    int n4 = i & ((NN / 4) - 1);
    int b  = i >> 20;
    int n  = n4 << 2;
    unsigned mword = g_maskbits[(b << 7) + (n >> 5)];
    unsigned bits  = mword >> (n & 31);
    float4 v = __ldcs(&x4[(size_t)i]);
    v.x = (bits & 1u) ? v.x : 0.0f;
    v.y = (bits & 2u) ? v.y : 0.0f;
    v.z = (bits & 4u) ? v.z : 0.0f;
    v.w = (bits & 8u) ? v.w : 0.0f;
    __stwt(&o4[(size_t)i], v);
}

// ---------------------------------------------------------------------------
extern "C" void kernel_launch(void* const* d_in, const int* in_sizes, int n_in,
                              void* d_out, int out_size) {
    const float* x = (const float*)d_in[0];
    float* out = (float*)d_out;

    // Kernel 1: B*T*N = 524288 threads
    k_partial<<<(BB * TT * NN) / 256, 256>>>(x);

    // Kernel 2: one 1024-thread block per batch
    k_select<<<BB, 1024>>>();

    // Kernel 3: 8388608 float4 elements, 1 per thread
    k_mask<<<(BB * TT * CC * NN / 4) / 256, 256>>>(
        (const float4*)x, (float4*)out);
}